// round 15
// baseline (speedup 1.0000x reference)
#include <cuda_runtime.h>
#include <cstdint>
#include <math.h>

#define Bq 64
#define Sq 384
#define Eq 64
#define Dq 50
#define Gq 256   // 4*E
#define SL 192   // attention rows per cluster CTA (Sq/2)

// scratch (allocation-free rule: __device__ globals)
__device__ float g_h1[Bq*Sq*Eq];
__device__ float g_c1[Bq*Sq*Eq];
__device__ float g_out[Bq*Sq*Eq];
__device__ float g_base[Bq*Sq*Eq];
__device__ float g_Rt[Bq*Sq*Eq];
__device__ float g_xp1[Bq*Sq*Gq];
__device__ float g_xp2[Bq*Sq*Gq];

// ---- fast transcendentals (err ~1e-6, well under the 1e-3 gate) ----------
__device__ __forceinline__ float rcp_fast(float x){
    float r; asm("rcp.approx.f32 %0, %1;" : "=f"(r) : "f"(x)); return r;
}
__device__ __forceinline__ float ftanh(float x){
    float t = __expf(-2.f * fabsf(x));
    float y = (1.f - t) * rcp_fast(1.f + t);
    return copysignf(y, x);
}
__device__ __forceinline__ float fsig(float x){
    return rcp_fast(1.f + __expf(-x));
}
__device__ __forceinline__ uint32_t smem_u32(const void* p){
    uint32_t a;
    asm("{ .reg .u64 t; cvta.to.shared.u64 t, %1; cvt.u32.u64 %0, t; }"
        : "=r"(a) : "l"(p));
    return a;
}
__device__ __forceinline__ uint32_t mapa_u32(uint32_t addr, uint32_t rank){
    uint32_t r;
    asm("mapa.shared::cluster.u32 %0, %1, %2;" : "=r"(r) : "r"(addr), "r"(rank));
    return r;
}
__device__ __forceinline__ void st_cluster_f32(uint32_t addr, float v){
    asm volatile("st.shared::cluster.f32 [%0], %1;" :: "r"(addr), "f"(v) : "memory");
}
__device__ __forceinline__ void mbar_init(uint32_t addr, uint32_t count){
    asm volatile("mbarrier.init.shared.b64 [%0], %1;" :: "r"(addr), "r"(count) : "memory");
}
__device__ __forceinline__ void mbar_arrive_remote(uint32_t addr){
    asm volatile("mbarrier.arrive.release.cluster.shared::cluster.b64 _, [%0];"
                 :: "r"(addr) : "memory");
}
__device__ __forceinline__ void mbar_wait_parity(uint32_t addr, uint32_t parity){
    uint32_t done;
    asm volatile(
        "{\n\t.reg .pred p;\n\t"
        "mbarrier.try_wait.parity.acquire.cluster.shared::cta.b64 p, [%1], %2;\n\t"
        "selp.b32 %0, 1, 0, p;\n\t}"
        : "=r"(done) : "r"(addr), "r"(parity) : "memory");
    while (!done) {
        asm volatile(
            "{\n\t.reg .pred p;\n\t"
            "mbarrier.try_wait.parity.acquire.cluster.shared::cta.b64 p, [%1], %2, 0x989680;\n\t"
            "selp.b32 %0, 1, 0, p;\n\t}"
            : "=r"(done) : "r"(addr), "r"(parity) : "memory");
    }
}
__device__ __forceinline__ void cluster_sync(){
    asm volatile("barrier.cluster.arrive.aligned;" ::: "memory");
    asm volatile("barrier.cluster.wait.aligned;"   ::: "memory");
}

// ---- packed f32x2 helpers (sm_103a) ---------------------------------------
#define ONE2 0x3f8000003f800000ULL
__device__ __forceinline__ uint64_t pack2(float lo, float hi){
    uint64_t r; asm("mov.b64 %0, {%1,%2};" : "=l"(r) : "f"(lo), "f"(hi)); return r;
}
__device__ __forceinline__ void unpack2(uint64_t v, float& lo, float& hi){
    asm("mov.b64 {%0,%1}, %2;" : "=f"(lo), "=f"(hi) : "l"(v));
}
__device__ __forceinline__ uint64_t fma2(uint64_t a, uint64_t b, uint64_t c){
    uint64_t r; asm("fma.rn.f32x2 %0, %1, %2, %3;" : "=l"(r) : "l"(a), "l"(b), "l"(c));
    return r;
}
__device__ __forceinline__ uint64_t add2(uint64_t a, uint64_t b){
    uint64_t r; asm("add.rn.f32x2 %0, %1, %2;" : "=l"(r) : "l"(a), "l"(b));
    return r;
}

// ---------------------------------------------------------------------------
// Input projection (both sentences in one launch; blockIdx.y selects set):
// xp[b,s,g] = emb[tok[b,s]] @ Wih[g,:] + bih[g] + bhh[g]
// ---------------------------------------------------------------------------
__global__ __launch_bounds__(256) void xproj_kernel(
    const int* __restrict__ t1, const int* __restrict__ t2,
    const float* __restrict__ emb,
    const float* __restrict__ Wih1, const float* __restrict__ bih1,
    const float* __restrict__ bhh1,
    const float* __restrict__ Wih2, const float* __restrict__ bih2,
    const float* __restrict__ bhh2,
    float* __restrict__ xp1, float* __restrict__ xp2)
{
    __shared__ float xs[32][Dq];
    __shared__ int   tk[32];
    int set = blockIdx.y;
    const int*   toks = set ? t2 : t1;
    const float* Wih  = set ? Wih2 : Wih1;
    const float* bih  = set ? bih2 : bih1;
    const float* bhh  = set ? bhh2 : bhh1;
    float*       xp   = set ? xp2 : xp1;

    int row0 = blockIdx.x * 32;
    int j = threadIdx.x;

    if (j < 32) tk[j] = toks[row0 + j];
    __syncthreads();
    for (int i = j; i < 32*Dq; i += 256) {
        int r = i / Dq, k = i % Dq;
        xs[r][k] = emb[tk[r]*Dq + k];
    }

    float w[Dq];
#pragma unroll
    for (int k = 0; k < Dq; k++) w[k] = Wih[j*Dq + k];
    float bias = bih[j] + bhh[j];
    __syncthreads();

#pragma unroll 4
    for (int r = 0; r < 32; r++) {
        float acc = bias;
#pragma unroll
        for (int k = 0; k < Dq; k++) acc += w[k]*xs[r][k];
        xp[(row0 + r)*Gq + j] = acc;
    }
}

// ---------------------------------------------------------------------------
// FUSED recurrent LSTM: one CTA per batch b runs LSTM1 then LSTM2 (phase 2's
// gather reads only this CTA's own phase-1 output — same-thread RAW through
// gmem, no inter-CTA dependency). Per phase: R6 best-measured shape.
// ---------------------------------------------------------------------------
__global__ __launch_bounds__(256) void lstm_fused_kernel(
    const float* __restrict__ xp1, const float* __restrict__ Whh1,
    const float* __restrict__ xp2, const float* __restrict__ Whh2,
    const int* __restrict__ iidx)
{
    __shared__ __align__(16) float hs[Eq];
    __shared__ float gs[Gq];

    int b = blockIdx.x, j = threadIdx.x;
    float whh[Eq];

    // ---- phase 1: LSTM1, zero init, writes g_h1 and g_c1 ----
#pragma unroll
    for (int k = 0; k < Eq; k++) whh[k] = Whh1[j*Eq + k];
    float c = 0.f;
    if (j < Eq) hs[j] = 0.f;
    __syncthreads();

    {
        const float* xpb = xp1 + (size_t)b*Sq*Gq + j;
        float xv = xpb[0];
        for (int t = 0; t < Sq; t++) {
            const float4* h4 = (const float4*)hs;
            float a0 = xv, a1 = 0.f, a2 = 0.f, a3 = 0.f;
#pragma unroll
            for (int k = 0; k < 4; k++) {
                float4 v0 = h4[4*k], v1 = h4[4*k+1], v2 = h4[4*k+2], v3 = h4[4*k+3];
                a0 += whh[16*k   ]*v0.x + whh[16*k+1 ]*v0.y + whh[16*k+2 ]*v0.z + whh[16*k+3 ]*v0.w;
                a1 += whh[16*k+4 ]*v1.x + whh[16*k+5 ]*v1.y + whh[16*k+6 ]*v1.z + whh[16*k+7 ]*v1.w;
                a2 += whh[16*k+8 ]*v2.x + whh[16*k+9 ]*v2.y + whh[16*k+10]*v2.z + whh[16*k+11]*v2.w;
                a3 += whh[16*k+12]*v3.x + whh[16*k+13]*v3.y + whh[16*k+14]*v3.z + whh[16*k+15]*v3.w;
            }
            float acc = (a0 + a1) + (a2 + a3);
            if (t + 1 < Sq) xv = xpb[(t+1)*Gq];
            gs[j] = acc;
            __syncthreads();

            if (j < Eq) {
                float ig = fsig(gs[j]);
                float fg = fsig(gs[Eq + j]);
                float gg = ftanh(gs[2*Eq + j]);
                float og = fsig(gs[3*Eq + j]);
                c = fg*c + ig*gg;
                float h = og*ftanh(c);
                hs[j] = h;
                g_h1[(b*Sq + t)*Eq + j] = h;
                g_c1[(b*Sq + t)*Eq + j] = c;
            }
            __syncthreads();
        }
    }

    // ---- phase 2: LSTM2, gathered init (own CTA's data), writes g_out ----
#pragma unroll
    for (int k = 0; k < Eq; k++) whh[k] = Whh2[j*Eq + k];
    c = 0.f;
    if (j < Eq) {
        int idx = iidx[b*Eq + j];          // s1_len is (B,1,E)
        hs[j] = g_h1[(b*Sq + idx)*Eq + j]; // written by THIS thread in phase 1
        c     = g_c1[(b*Sq + idx)*Eq + j];
    }
    __syncthreads();

    {
        const float* xpb = xp2 + (size_t)b*Sq*Gq + j;
        float xv = xpb[0];
        for (int t = 0; t < Sq; t++) {
            const float4* h4 = (const float4*)hs;
            float a0 = xv, a1 = 0.f, a2 = 0.f, a3 = 0.f;
#pragma unroll
            for (int k = 0; k < 4; k++) {
                float4 v0 = h4[4*k], v1 = h4[4*k+1], v2 = h4[4*k+2], v3 = h4[4*k+3];
                a0 += whh[16*k   ]*v0.x + whh[16*k+1 ]*v0.y + whh[16*k+2 ]*v0.z + whh[16*k+3 ]*v0.w;
                a1 += whh[16*k+4 ]*v1.x + whh[16*k+5 ]*v1.y + whh[16*k+6 ]*v1.z + whh[16*k+7 ]*v1.w;
                a2 += whh[16*k+8 ]*v2.x + whh[16*k+9 ]*v2.y + whh[16*k+10]*v2.z + whh[16*k+11]*v2.w;
                a3 += whh[16*k+12]*v3.x + whh[16*k+13]*v3.y + whh[16*k+14]*v3.z + whh[16*k+15]*v3.w;
            }
            float acc = (a0 + a1) + (a2 + a3);
            if (t + 1 < Sq) xv = xpb[(t+1)*Gq];
            gs[j] = acc;
            __syncthreads();

            if (j < Eq) {
                float ig = fsig(gs[j]);
                float fg = fsig(gs[Eq + j]);
                float gg = ftanh(gs[2*Eq + j]);
                float og = fsig(gs[3*Eq + j]);
                c = fg*c + ig*gg;
                float h = og*ftanh(c);
                hs[j] = h;
                g_out[(b*Sq + t)*Eq + j] = h;
            }
            __syncthreads();
        }
    }
}

// ---------------------------------------------------------------------------
// base[b,s,:] = h1[b,s,:] @ wy + out[b,s,:] @ wh
// ---------------------------------------------------------------------------
__global__ __launch_bounds__(256) void base_kernel(
    const float* __restrict__ wy, const float* __restrict__ wh)
{
    __shared__ float wys[Eq*Eq], whs[Eq*Eq];
    __shared__ float ht[16][Eq], ot[16][Eq];

    int b  = blockIdx.y;
    int s0 = blockIdx.x * 16;
    int tid = threadIdx.x;

    for (int i = tid; i < Eq*Eq; i += 256) { wys[i] = wy[i]; whs[i] = wh[i]; }
    for (int i = tid; i < 16*Eq; i += 256) {
        int s = i >> 6, k = i & 63;
        ht[s][k] = g_h1 [(b*Sq + s0 + s)*Eq + k];
        ot[s][k] = g_out[(b*Sq + s0 + s)*Eq + k];
    }
    __syncthreads();

    int sl = tid >> 4;
    int e0 = (tid & 15) * 4;
    float acc[4] = {0.f, 0.f, 0.f, 0.f};
#pragma unroll 8
    for (int k = 0; k < Eq; k++) {
        float hv = ht[sl][k], ov = ot[sl][k];
#pragma unroll
        for (int u = 0; u < 4; u++)
            acc[u] += hv*wys[k*Eq + e0 + u] + ov*whs[k*Eq + e0 + u];
    }
    float* dst = &g_base[(b*Sq + s0 + sl)*Eq + e0];
#pragma unroll
    for (int u = 0; u < 4; u++) dst[u] = acc[u];
}

// ---------------------------------------------------------------------------
// Attention scan, 2-CTA cluster per batch row.
// Loop-invariant registers: tb/wtb PACKED as f32x2 (u64), hreg[32].
// p2 uses packed fma.rn.f32x2/add.rn.f32x2 for b_i, wa_i + quad-rcp tree.
// ---------------------------------------------------------------------------
#define ATT_FLOATS (4 + 2*68 + 4 + 4*64 + 12*64 + 16)
#define ATT_SMEM   (ATT_FLOATS*4)

__global__ __launch_bounds__(384) __cluster_dims__(2, 1, 1)
void attn_kernel(
    const float* __restrict__ wvec, const float* __restrict__ wr,
    const float* __restrict__ wt,   const float* __restrict__ s1s)
{
    extern __shared__ float sm[];
    // sm[0..3]: mbarrier (8B) + pad
    float* imp    = sm + 4;              // 2*68 import slots (peer writes here)
    float* r_s    = imp + 2*68 + 4;      // 64 (16B aligned: 4+136+4 = 144)
    float* tr_s   = r_s + 64;            // 64  raw tanh(r@wr)
    float* wtr_s  = tr_s + 64;           // 64  w*tanh(r@wr)
    float* trwt_s = wtr_s + 64;          // 64  tanh(r@wt)
    float* part   = trwt_s + 64;         // 12*64
    float* red    = part + 12*64;        // 16

    int cta  = blockIdx.x;
    int b    = cta >> 1;
    uint32_t rank = cta & 1u;
    int tid  = threadIdx.x;
    int lane = tid & 31, wid = tid >> 5;

    uint32_t mbar_local  = smem_u32(sm);
    uint32_t mbar_remote = mapa_u32(mbar_local, rank ^ 1u);
    uint32_t imp_remote  = mapa_u32(smem_u32(imp), rank ^ 1u);

    if (tid == 0) mbar_init(mbar_local, 64);

    int half = lane & 1;
    int row  = wid*16 + (lane >> 1);     // p2 row for this thread (0..191)

    // p1 weights: thread tid<256 -> output o=tid>>1, rows hh*32..+32
    float wcol[32];
    float wv_o = 0.f;
    if (tid < 256) {
        int o = tid >> 1, hh = tid & 1;
        const float* wsrc = (o < 64) ? (wr + o) : (wt + o - 64);
#pragma unroll
        for (int k = 0; k < 32; k++) wcol[k] = wsrc[(hh*32 + k)*Eq];
        if (o < 64 && hh == 0) wv_o = wvec[o];
    }

    const int gofs = b*Sq*Eq + (int)rank*SL*Eq;

    // loop-invariant per-thread registers: tb and wtb PACKED as f32x2
    uint64_t tb2[16], wtb2[16];
    {
        const float* bsrc = &g_base[gofs + row*Eq + half*32];
        const float* wsrc = wvec + half*32;
#pragma unroll
        for (int k = 0; k < 16; k++) {
            float t0 = ftanh(bsrc[2*k]);
            float t1 = ftanh(bsrc[2*k+1]);
            tb2[k]  = pack2(t0, t1);
            wtb2[k] = pack2(wsrc[2*k]*t0, wsrc[2*k+1]*t1);
        }
    }
    // loop-invariant h registers for p3: rows wid*16..+15, cols 2*lane..+1
    float hreg[32];
    {
        const float* hsrc = &g_h1[gofs + (wid*16)*Eq + lane*2];
#pragma unroll
        for (int si = 0; si < 16; si++) {
            float2 hv = *(const float2*)&hsrc[si*Eq];
            hreg[2*si]   = hv.x;
            hreg[2*si+1] = hv.y;
        }
    }
    float m1 = s1s[b*Sq + (int)rank*SL + row];
    if (tid < 64) r_s[tid] = 0.f;
    __syncthreads();
    cluster_sync();   // peer's mbarrier init visible before any remote arrive

    for (int t = 0; t < Sq; t++) {
        // p1: tr = tanh(r@wr) (+ w-scaled), trwt = tanh(r@wt); 2 thr/output
        if (tid < 256) {
            int o = tid >> 1, hh = tid & 1;
            const float4* r4 = (const float4*)(r_s + hh*32);
            float a0 = 0.f, a1 = 0.f;
#pragma unroll
            for (int q = 0; q < 8; q += 2) {
                float4 v0 = r4[q], v1 = r4[q+1];
                a0 += wcol[4*q  ]*v0.x + wcol[4*q+1]*v0.y
                    + wcol[4*q+2]*v0.z + wcol[4*q+3]*v0.w;
                a1 += wcol[4*q+4]*v1.x + wcol[4*q+5]*v1.y
                    + wcol[4*q+6]*v1.z + wcol[4*q+7]*v1.w;
            }
            float s_ = a0 + a1;
            s_ += __shfl_xor_sync(0xffffffffu, s_, 1);
            if (hh == 0) {
                float v = ftanh(s_);
                if (o < 64) { tr_s[o] = v; wtr_s[o] = wv_o*v; }
                else trwt_s[o-64] = v;
            }
        }
        __syncthreads();

        // p2: score for `row` (2 threads/row, 32 elems each)
        // packed b/wa + quad-rcp tree
        float sc = 0.f;
        {
            const ulonglong2* tr2 = (const ulonglong2*)(tr_s  + half*32);
            const ulonglong2* wr2 = (const ulonglong2*)(wtr_s + half*32);
#pragma unroll
            for (int q = 0; q < 8; q++) {
                ulonglong2 tvp = tr2[q];
                ulonglong2 wvp = wr2[q];
                uint64_t b01 = fma2(tb2[2*q],   tvp.x, ONE2);
                uint64_t b23 = fma2(tb2[2*q+1], tvp.y, ONE2);
                uint64_t wa01 = add2(wtb2[2*q],   wvp.x);
                uint64_t wa23 = add2(wtb2[2*q+1], wvp.y);
                float b0, b1, b2, b3, wa0, wa1, wa2, wa3;
                unpack2(b01, b0, b1);   unpack2(b23, b2, b3);
                unpack2(wa01, wa0, wa1); unpack2(wa23, wa2, wa3);
                float d01 = b0*b1, d23 = b2*b3;
                float n01 = fmaf(wa1, b0, wa0*b1);
                float n23 = fmaf(wa3, b2, wa2*b3);
                float num = fmaf(n23, d01, n01*d23);
                sc = fmaf(num, rcp_fast(d01*d23), sc);
            }
        }
        sc += __shfl_xor_sync(0xffffffffu, sc, 1);
        sc = m1*sc - (1.f - m1)*1e12f;
        float p = __expf(sc);

        // warp sum of p (each p duplicated in a lane pair -> halve)
        float v = p;
#pragma unroll
        for (int o = 16; o > 0; o >>= 1) v += __shfl_xor_sync(0xffffffffu, v, o);
        if (lane == 0) red[wid] = 0.5f*v;

        // p3: h.p partials from REGISTERS (16 rows x 2 e-cols per thread)
        {
            float a0 = 0.f, a1 = 0.f;
#pragma unroll
            for (int si = 0; si < 16; si++) {
                float pv = __shfl_sync(0xffffffffu, p, 2*si);
                a0 = fmaf(hreg[2*si],   pv, a0);
                a1 = fmaf(hreg[2*si+1], pv, a1);
            }
            part[wid*64 + lane*2]     = a0;
            part[wid*64 + lane*2 + 1] = a1;
        }
        __syncthreads();

        // p5: combine partials, exchange with peer, update r
        if (tid < 64) {
            float nl = 0.f;
#pragma unroll
            for (int g = 0; g < 12; g++) nl += part[g*64 + tid];
            float sl_ = 0.f;
#pragma unroll
            for (int i = 0; i < 12; i++) sl_ += red[i];

            int slot = (t & 1) * 68;
            st_cluster_f32(imp_remote + (slot + tid)*4, nl);
            if (tid == 0) st_cluster_f32(imp_remote + (slot + 64)*4, sl_);
            mbar_arrive_remote(mbar_remote);           // release (64 arrivals)
            mbar_wait_parity(mbar_local, (uint32_t)(t & 1));

            float pn = imp[slot + tid];
            float ps = imp[slot + 64];
            float rn = (nl + pn)*rcp_fast(sl_ + ps) + trwt_s[tid];
            r_s[tid] = rn;
            if (rank == 0) g_Rt[(b*Sq + t)*Eq + tid] = rn;
        }
        __syncthreads();
    }
    cluster_sync();   // no CTA exits while peer may still write our smem
}

// ---------------------------------------------------------------------------
// Final gathers + MLP head
// ---------------------------------------------------------------------------
__global__ __launch_bounds__(128) void final_kernel(
    const int* __restrict__ s2len,
    const float* __restrict__ wp, const float* __restrict__ wx,
    const float* __restrict__ l1W, const float* __restrict__ l1b,
    const float* __restrict__ lW,  const float* __restrict__ lb,
    float* __restrict__ outp)
{
    __shared__ float rn[64], hn[64], hid[64], h2[128];
    int b = blockIdx.x, tid = threadIdx.x;

    if (tid < 64) {
        int idx = s2len[b*64 + tid];
        rn[tid] = g_Rt [(b*Sq + idx)*Eq + tid];
        hn[tid] = g_out[(b*Sq + idx)*Eq + tid];
    }
    __syncthreads();
    if (tid < 64) {
        float a = 0.f;
#pragma unroll 8
        for (int e = 0; e < 64; e++)
            a += rn[e]*wp[e*64 + tid] + hn[e]*wx[e*64 + tid];
        hid[tid] = ftanh(a);
    }
    __syncthreads();
    {
        float a = l1b[tid];
#pragma unroll 8
        for (int f = 0; f < 64; f++) a += hid[f]*l1W[tid*64 + f];
        h2[tid] = ftanh(a);
    }
    __syncthreads();
    if (tid < 4) {
        float a = lb[tid];
#pragma unroll 8
        for (int j = 0; j < 128; j++) a += h2[j]*lW[tid*128 + j];
        outp[b*4 + tid] = a;
    }
}

// ---------------------------------------------------------------------------
extern "C" void kernel_launch(void* const* d_in, const int* in_sizes, int n_in,
                              void* d_out, int out_size)
{
    (void)in_sizes; (void)n_in; (void)out_size;

    const int*   s1   = (const int*)d_in[0];
    const int*   s2   = (const int*)d_in[1];
    const int*   s1l  = (const int*)d_in[2];
    const int*   s2l  = (const int*)d_in[3];
    const float* s1s  = (const float*)d_in[4];
    /* d_in[5] = s2_s, unused by the reference */
    const float* emb  = (const float*)d_in[6];
    const float* Wih1 = (const float*)d_in[7];
    const float* Whh1 = (const float*)d_in[8];
    const float* bih1 = (const float*)d_in[9];
    const float* bhh1 = (const float*)d_in[10];
    const float* Wih2 = (const float*)d_in[11];
    const float* Whh2 = (const float*)d_in[12];
    const float* bih2 = (const float*)d_in[13];
    const float* bhh2 = (const float*)d_in[14];
    const float* wy   = (const float*)d_in[15];
    const float* wh   = (const float*)d_in[16];
    const float* wv   = (const float*)d_in[17];
    const float* wp   = (const float*)d_in[18];
    const float* wx   = (const float*)d_in[19];
    const float* wr   = (const float*)d_in[20];
    const float* wt   = (const float*)d_in[21];
    const float* l1W  = (const float*)d_in[22];
    const float* l1b  = (const float*)d_in[23];
    const float* lW   = (const float*)d_in[24];
    const float* lb   = (const float*)d_in[25];
    float* outp = (float*)d_out;

    cudaFuncSetAttribute(attn_kernel,
                         cudaFuncAttributeMaxDynamicSharedMemorySize, ATT_SMEM);

    float* xp1; cudaGetSymbolAddress((void**)&xp1, g_xp1);
    float* xp2; cudaGetSymbolAddress((void**)&xp2, g_xp2);

    xproj_kernel<<<dim3((Bq*Sq)/32, 2), 256>>>(
        s1, s2, emb, Wih1, bih1, bhh1, Wih2, bih2, bhh2, xp1, xp2);
    lstm_fused_kernel<<<Bq, 256>>>(xp1, Whh1, xp2, Whh2, s1l);
    base_kernel<<<dim3(24, Bq), 256>>>(wy, wh);
    attn_kernel<<<Bq*2, 384, ATT_SMEM>>>(wv, wr, wt, s1s);
    final_kernel<<<Bq, 128>>>(s2l, wp, wx, l1W, l1b, lW, lb, outp);
}

// round 16
// speedup vs baseline: 1.0061x; 1.0061x over previous
#include <cuda_runtime.h>
#include <cstdint>
#include <math.h>

#define Bq 64
#define Sq 384
#define Eq 64
#define Dq 50
#define Gq 256   // 4*E
#define SL 192   // attention rows per cluster CTA (Sq/2)

// scratch (allocation-free rule: __device__ globals)
__device__ float g_h1[Bq*Sq*Eq];
__device__ float g_c1[Bq*Sq*Eq];
__device__ float g_out[Bq*Sq*Eq];
__device__ float g_base[Bq*Sq*Eq];
__device__ float g_Rt[Bq*Sq*Eq];
__device__ float g_xp1[Bq*Sq*Gq];
__device__ float g_xp2[Bq*Sq*Gq];

// ---- fast transcendentals (err ~1e-6, well under the 1e-3 gate) ----------
__device__ __forceinline__ float rcp_fast(float x){
    float r; asm("rcp.approx.f32 %0, %1;" : "=f"(r) : "f"(x)); return r;
}
__device__ __forceinline__ float ftanh(float x){
    float t = __expf(-2.f * fabsf(x));
    float y = (1.f - t) * rcp_fast(1.f + t);
    return copysignf(y, x);
}
__device__ __forceinline__ float fsig(float x){
    return rcp_fast(1.f + __expf(-x));
}
__device__ __forceinline__ uint32_t smem_u32(const void* p){
    uint32_t a;
    asm("{ .reg .u64 t; cvta.to.shared.u64 t, %1; cvt.u32.u64 %0, t; }"
        : "=r"(a) : "l"(p));
    return a;
}
__device__ __forceinline__ uint32_t mapa_u32(uint32_t addr, uint32_t rank){
    uint32_t r;
    asm("mapa.shared::cluster.u32 %0, %1, %2;" : "=r"(r) : "r"(addr), "r"(rank));
    return r;
}
__device__ __forceinline__ void st_cluster_f32(uint32_t addr, float v){
    asm volatile("st.shared::cluster.f32 [%0], %1;" :: "r"(addr), "f"(v) : "memory");
}
__device__ __forceinline__ void mbar_init(uint32_t addr, uint32_t count){
    asm volatile("mbarrier.init.shared.b64 [%0], %1;" :: "r"(addr), "r"(count) : "memory");
}
__device__ __forceinline__ void mbar_arrive_remote(uint32_t addr){
    asm volatile("mbarrier.arrive.release.cluster.shared::cluster.b64 _, [%0];"
                 :: "r"(addr) : "memory");
}
__device__ __forceinline__ void mbar_wait_parity(uint32_t addr, uint32_t parity){
    uint32_t done;
    asm volatile(
        "{\n\t.reg .pred p;\n\t"
        "mbarrier.try_wait.parity.acquire.cluster.shared::cta.b64 p, [%1], %2;\n\t"
        "selp.b32 %0, 1, 0, p;\n\t}"
        : "=r"(done) : "r"(addr), "r"(parity) : "memory");
    while (!done) {
        asm volatile(
            "{\n\t.reg .pred p;\n\t"
            "mbarrier.try_wait.parity.acquire.cluster.shared::cta.b64 p, [%1], %2, 0x989680;\n\t"
            "selp.b32 %0, 1, 0, p;\n\t}"
            : "=r"(done) : "r"(addr), "r"(parity) : "memory");
    }
}
__device__ __forceinline__ void cluster_sync(){
    asm volatile("barrier.cluster.arrive.aligned;" ::: "memory");
    asm volatile("barrier.cluster.wait.aligned;"   ::: "memory");
}

// ---------------------------------------------------------------------------
// Input projection (both sentences in one launch; blockIdx.y selects set):
// xp[b,s,g] = emb[tok[b,s]] @ Wih[g,:] + bih[g] + bhh[g]
// ---------------------------------------------------------------------------
__global__ __launch_bounds__(256) void xproj_kernel(
    const int* __restrict__ t1, const int* __restrict__ t2,
    const float* __restrict__ emb,
    const float* __restrict__ Wih1, const float* __restrict__ bih1,
    const float* __restrict__ bhh1,
    const float* __restrict__ Wih2, const float* __restrict__ bih2,
    const float* __restrict__ bhh2,
    float* __restrict__ xp1, float* __restrict__ xp2)
{
    __shared__ float xs[32][Dq];
    __shared__ int   tk[32];
    int set = blockIdx.y;
    const int*   toks = set ? t2 : t1;
    const float* Wih  = set ? Wih2 : Wih1;
    const float* bih  = set ? bih2 : bih1;
    const float* bhh  = set ? bhh2 : bhh1;
    float*       xp   = set ? xp2 : xp1;

    int row0 = blockIdx.x * 32;
    int j = threadIdx.x;

    if (j < 32) tk[j] = toks[row0 + j];
    __syncthreads();
    for (int i = j; i < 32*Dq; i += 256) {
        int r = i / Dq, k = i % Dq;
        xs[r][k] = emb[tk[r]*Dq + k];
    }

    float w[Dq];
#pragma unroll
    for (int k = 0; k < Dq; k++) w[k] = Wih[j*Dq + k];
    float bias = bih[j] + bhh[j];
    __syncthreads();

#pragma unroll 4
    for (int r = 0; r < 32; r++) {
        float acc = bias;
#pragma unroll
        for (int k = 0; k < Dq; k++) acc += w[k]*xs[r][k];
        xp[(row0 + r)*Gq + j] = acc;
    }
}

// ---------------------------------------------------------------------------
// FUSED recurrent LSTM: one CTA per batch b runs LSTM1 then LSTM2 (phase 2's
// gather reads only this CTA's own phase-1 output — same-thread RAW through
// gmem, no inter-CTA dependency). Per phase: R6 best-measured shape.
// ---------------------------------------------------------------------------
__global__ __launch_bounds__(256) void lstm_fused_kernel(
    const float* __restrict__ xp1, const float* __restrict__ Whh1,
    const float* __restrict__ xp2, const float* __restrict__ Whh2,
    const int* __restrict__ iidx)
{
    __shared__ __align__(16) float hs[Eq];
    __shared__ float gs[Gq];

    int b = blockIdx.x, j = threadIdx.x;
    float whh[Eq];

    // ---- phase 1: LSTM1, zero init, writes g_h1 and g_c1 ----
#pragma unroll
    for (int k = 0; k < Eq; k++) whh[k] = Whh1[j*Eq + k];
    float c = 0.f;
    if (j < Eq) hs[j] = 0.f;
    __syncthreads();

    {
        const float* xpb = xp1 + (size_t)b*Sq*Gq + j;
        float xv = xpb[0];
        for (int t = 0; t < Sq; t++) {
            const float4* h4 = (const float4*)hs;
            float a0 = xv, a1 = 0.f, a2 = 0.f, a3 = 0.f;
#pragma unroll
            for (int k = 0; k < 4; k++) {
                float4 v0 = h4[4*k], v1 = h4[4*k+1], v2 = h4[4*k+2], v3 = h4[4*k+3];
                a0 += whh[16*k   ]*v0.x + whh[16*k+1 ]*v0.y + whh[16*k+2 ]*v0.z + whh[16*k+3 ]*v0.w;
                a1 += whh[16*k+4 ]*v1.x + whh[16*k+5 ]*v1.y + whh[16*k+6 ]*v1.z + whh[16*k+7 ]*v1.w;
                a2 += whh[16*k+8 ]*v2.x + whh[16*k+9 ]*v2.y + whh[16*k+10]*v2.z + whh[16*k+11]*v2.w;
                a3 += whh[16*k+12]*v3.x + whh[16*k+13]*v3.y + whh[16*k+14]*v3.z + whh[16*k+15]*v3.w;
            }
            float acc = (a0 + a1) + (a2 + a3);
            if (t + 1 < Sq) xv = xpb[(t+1)*Gq];
            gs[j] = acc;
            __syncthreads();

            if (j < Eq) {
                float ig = fsig(gs[j]);
                float fg = fsig(gs[Eq + j]);
                float gg = ftanh(gs[2*Eq + j]);
                float og = fsig(gs[3*Eq + j]);
                c = fg*c + ig*gg;
                float h = og*ftanh(c);
                hs[j] = h;
                g_h1[(b*Sq + t)*Eq + j] = h;
                g_c1[(b*Sq + t)*Eq + j] = c;
            }
            __syncthreads();
        }
    }

    // ---- phase 2: LSTM2, gathered init (own CTA's data), writes g_out ----
#pragma unroll
    for (int k = 0; k < Eq; k++) whh[k] = Whh2[j*Eq + k];
    c = 0.f;
    if (j < Eq) {
        int idx = iidx[b*Eq + j];          // s1_len is (B,1,E)
        hs[j] = g_h1[(b*Sq + idx)*Eq + j]; // written by THIS thread in phase 1
        c     = g_c1[(b*Sq + idx)*Eq + j];
    }
    __syncthreads();

    {
        const float* xpb = xp2 + (size_t)b*Sq*Gq + j;
        float xv = xpb[0];
        for (int t = 0; t < Sq; t++) {
            const float4* h4 = (const float4*)hs;
            float a0 = xv, a1 = 0.f, a2 = 0.f, a3 = 0.f;
#pragma unroll
            for (int k = 0; k < 4; k++) {
                float4 v0 = h4[4*k], v1 = h4[4*k+1], v2 = h4[4*k+2], v3 = h4[4*k+3];
                a0 += whh[16*k   ]*v0.x + whh[16*k+1 ]*v0.y + whh[16*k+2 ]*v0.z + whh[16*k+3 ]*v0.w;
                a1 += whh[16*k+4 ]*v1.x + whh[16*k+5 ]*v1.y + whh[16*k+6 ]*v1.z + whh[16*k+7 ]*v1.w;
                a2 += whh[16*k+8 ]*v2.x + whh[16*k+9 ]*v2.y + whh[16*k+10]*v2.z + whh[16*k+11]*v2.w;
                a3 += whh[16*k+12]*v3.x + whh[16*k+13]*v3.y + whh[16*k+14]*v3.z + whh[16*k+15]*v3.w;
            }
            float acc = (a0 + a1) + (a2 + a3);
            if (t + 1 < Sq) xv = xpb[(t+1)*Gq];
            gs[j] = acc;
            __syncthreads();

            if (j < Eq) {
                float ig = fsig(gs[j]);
                float fg = fsig(gs[Eq + j]);
                float gg = ftanh(gs[2*Eq + j]);
                float og = fsig(gs[3*Eq + j]);
                c = fg*c + ig*gg;
                float h = og*ftanh(c);
                hs[j] = h;
                g_out[(b*Sq + t)*Eq + j] = h;
            }
            __syncthreads();
        }
    }
}

// ---------------------------------------------------------------------------
// base[b,s,:] = h1[b,s,:] @ wy + out[b,s,:] @ wh
// ---------------------------------------------------------------------------
__global__ __launch_bounds__(256) void base_kernel(
    const float* __restrict__ wy, const float* __restrict__ wh)
{
    __shared__ float wys[Eq*Eq], whs[Eq*Eq];
    __shared__ float ht[16][Eq], ot[16][Eq];

    int b  = blockIdx.y;
    int s0 = blockIdx.x * 16;
    int tid = threadIdx.x;

    for (int i = tid; i < Eq*Eq; i += 256) { wys[i] = wy[i]; whs[i] = wh[i]; }
    for (int i = tid; i < 16*Eq; i += 256) {
        int s = i >> 6, k = i & 63;
        ht[s][k] = g_h1 [(b*Sq + s0 + s)*Eq + k];
        ot[s][k] = g_out[(b*Sq + s0 + s)*Eq + k];
    }
    __syncthreads();

    int sl = tid >> 4;
    int e0 = (tid & 15) * 4;
    float acc[4] = {0.f, 0.f, 0.f, 0.f};
#pragma unroll 8
    for (int k = 0; k < Eq; k++) {
        float hv = ht[sl][k], ov = ot[sl][k];
#pragma unroll
        for (int u = 0; u < 4; u++)
            acc[u] += hv*wys[k*Eq + e0 + u] + ov*whs[k*Eq + e0 + u];
    }
    float* dst = &g_base[(b*Sq + s0 + sl)*Eq + e0];
#pragma unroll
    for (int u = 0; u < 4; u++) dst[u] = acc[u];
}

// ---------------------------------------------------------------------------
// Attention scan, 2-CTA cluster per batch row (R14 best-measured form).
// Loop-invariant registers: tb[32], wtb[32] (scalar), hreg[32].
// p2 quad-rcp batching (1 MUFU / 4 elems); p3 from registers.
// ---------------------------------------------------------------------------
#define ATT_FLOATS (4 + 2*68 + 4 + 4*64 + 12*64 + 16)
#define ATT_SMEM   (ATT_FLOATS*4)

__global__ __launch_bounds__(384) __cluster_dims__(2, 1, 1)
void attn_kernel(
    const float* __restrict__ wvec, const float* __restrict__ wr,
    const float* __restrict__ wt,   const float* __restrict__ s1s)
{
    extern __shared__ float sm[];
    // sm[0..3]: mbarrier (8B) + pad
    float* imp    = sm + 4;              // 2*68 import slots (peer writes here)
    float* r_s    = imp + 2*68 + 4;      // 64 (16B aligned: 4+136+4 = 144)
    float* tr_s   = r_s + 64;            // 64  raw tanh(r@wr)
    float* wtr_s  = tr_s + 64;           // 64  w*tanh(r@wr)
    float* trwt_s = wtr_s + 64;          // 64  tanh(r@wt)
    float* part   = trwt_s + 64;         // 12*64
    float* red    = part + 12*64;        // 16

    int cta  = blockIdx.x;
    int b    = cta >> 1;
    uint32_t rank = cta & 1u;
    int tid  = threadIdx.x;
    int lane = tid & 31, wid = tid >> 5;

    uint32_t mbar_local  = smem_u32(sm);
    uint32_t mbar_remote = mapa_u32(mbar_local, rank ^ 1u);
    uint32_t imp_remote  = mapa_u32(smem_u32(imp), rank ^ 1u);

    if (tid == 0) mbar_init(mbar_local, 64);

    int half = lane & 1;
    int row  = wid*16 + (lane >> 1);     // p2 row for this thread (0..191)

    // p1 weights: thread tid<256 -> output o=tid>>1, rows hh*32..+32
    float wcol[32];
    float wv_o = 0.f;
    if (tid < 256) {
        int o = tid >> 1, hh = tid & 1;
        const float* wsrc = (o < 64) ? (wr + o) : (wt + o - 64);
#pragma unroll
        for (int k = 0; k < 32; k++) wcol[k] = wsrc[(hh*32 + k)*Eq];
        if (o < 64 && hh == 0) wv_o = wvec[o];
    }

    const int gofs = b*Sq*Eq + (int)rank*SL*Eq;

    // loop-invariant per-thread registers: raw tb and w-scaled wtb (p2 slice)
    float tb[32], wtb[32];
    {
        const float* bsrc = &g_base[gofs + row*Eq + half*32];
        const float* wsrc = wvec + half*32;
#pragma unroll
        for (int k = 0; k < 32; k++) {
            tb[k]  = ftanh(bsrc[k]);
            wtb[k] = wsrc[k]*tb[k];
        }
    }
    // loop-invariant h registers for p3: rows wid*16..+15, cols 2*lane..+1
    float hreg[32];
    {
        const float* hsrc = &g_h1[gofs + (wid*16)*Eq + lane*2];
#pragma unroll
        for (int si = 0; si < 16; si++) {
            float2 hv = *(const float2*)&hsrc[si*Eq];
            hreg[2*si]   = hv.x;
            hreg[2*si+1] = hv.y;
        }
    }
    float m1 = s1s[b*Sq + (int)rank*SL + row];
    if (tid < 64) r_s[tid] = 0.f;
    __syncthreads();
    cluster_sync();   // peer's mbarrier init visible before any remote arrive

    for (int t = 0; t < Sq; t++) {
        // p1: tr = tanh(r@wr) (+ w-scaled), trwt = tanh(r@wt); 2 thr/output
        if (tid < 256) {
            int o = tid >> 1, hh = tid & 1;
            const float4* r4 = (const float4*)(r_s + hh*32);
            float a0 = 0.f, a1 = 0.f;
#pragma unroll
            for (int q = 0; q < 8; q += 2) {
                float4 v0 = r4[q], v1 = r4[q+1];
                a0 += wcol[4*q  ]*v0.x + wcol[4*q+1]*v0.y
                    + wcol[4*q+2]*v0.z + wcol[4*q+3]*v0.w;
                a1 += wcol[4*q+4]*v1.x + wcol[4*q+5]*v1.y
                    + wcol[4*q+6]*v1.z + wcol[4*q+7]*v1.w;
            }
            float s_ = a0 + a1;
            s_ += __shfl_xor_sync(0xffffffffu, s_, 1);
            if (hh == 0) {
                float v = ftanh(s_);
                if (o < 64) { tr_s[o] = v; wtr_s[o] = wv_o*v; }
                else trwt_s[o-64] = v;
            }
        }
        __syncthreads();

        // p2: score for `row` (2 threads/row, 32 elems each), quad-rcp form
        float sc = 0.f;
        {
            const float4* tr4 = (const float4*)(tr_s  + half*32);
            const float4* wr4 = (const float4*)(wtr_s + half*32);
#pragma unroll
            for (int q = 0; q < 8; q++) {
                float4 tv = tr4[q], wv = wr4[q];
                float b0 = fmaf(tb[4*q  ], tv.x, 1.f);
                float b1 = fmaf(tb[4*q+1], tv.y, 1.f);
                float b2 = fmaf(tb[4*q+2], tv.z, 1.f);
                float b3 = fmaf(tb[4*q+3], tv.w, 1.f);
                float wa0 = wtb[4*q  ] + wv.x;
                float wa1 = wtb[4*q+1] + wv.y;
                float wa2 = wtb[4*q+2] + wv.z;
                float wa3 = wtb[4*q+3] + wv.w;
                float n01 = fmaf(wa1, b0, wa0*b1);
                float n23 = fmaf(wa3, b2, wa2*b3);
                float d01 = b0*b1, d23 = b2*b3;
                float num = fmaf(n23, d01, n01*d23);
                sc = fmaf(num, rcp_fast(d01*d23), sc);
            }
        }
        sc += __shfl_xor_sync(0xffffffffu, sc, 1);
        sc = m1*sc - (1.f - m1)*1e12f;
        float p = __expf(sc);

        // warp sum of p (each p duplicated in a lane pair -> halve)
        float v = p;
#pragma unroll
        for (int o = 16; o > 0; o >>= 1) v += __shfl_xor_sync(0xffffffffu, v, o);
        if (lane == 0) red[wid] = 0.5f*v;

        // p3: h.p partials from REGISTERS (16 rows x 2 e-cols per thread)
        {
            float a0 = 0.f, a1 = 0.f;
#pragma unroll
            for (int si = 0; si < 16; si++) {
                float pv = __shfl_sync(0xffffffffu, p, 2*si);
                a0 = fmaf(hreg[2*si],   pv, a0);
                a1 = fmaf(hreg[2*si+1], pv, a1);
            }
            part[wid*64 + lane*2]     = a0;
            part[wid*64 + lane*2 + 1] = a1;
        }
        __syncthreads();

        // p5: combine partials, exchange with peer, update r
        if (tid < 64) {
            float nl = 0.f;
#pragma unroll
            for (int g = 0; g < 12; g++) nl += part[g*64 + tid];
            float sl_ = 0.f;
#pragma unroll
            for (int i = 0; i < 12; i++) sl_ += red[i];

            int slot = (t & 1) * 68;
            st_cluster_f32(imp_remote + (slot + tid)*4, nl);
            if (tid == 0) st_cluster_f32(imp_remote + (slot + 64)*4, sl_);
            mbar_arrive_remote(mbar_remote);           // release (64 arrivals)
            mbar_wait_parity(mbar_local, (uint32_t)(t & 1));

            float pn = imp[slot + tid];
            float ps = imp[slot + 64];
            float rn = (nl + pn)*rcp_fast(sl_ + ps) + trwt_s[tid];
            r_s[tid] = rn;
            if (rank == 0) g_Rt[(b*Sq + t)*Eq + tid] = rn;
        }
        __syncthreads();
    }
    cluster_sync();   // no CTA exits while peer may still write our smem
}

// ---------------------------------------------------------------------------
// Final gathers + MLP head
// ---------------------------------------------------------------------------
__global__ __launch_bounds__(128) void final_kernel(
    const int* __restrict__ s2len,
    const float* __restrict__ wp, const float* __restrict__ wx,
    const float* __restrict__ l1W, const float* __restrict__ l1b,
    const float* __restrict__ lW,  const float* __restrict__ lb,
    float* __restrict__ outp)
{
    __shared__ float rn[64], hn[64], hid[64], h2[128];
    int b = blockIdx.x, tid = threadIdx.x;

    if (tid < 64) {
        int idx = s2len[b*64 + tid];
        rn[tid] = g_Rt [(b*Sq + idx)*Eq + tid];
        hn[tid] = g_out[(b*Sq + idx)*Eq + tid];
    }
    __syncthreads();
    if (tid < 64) {
        float a = 0.f;
#pragma unroll 8
        for (int e = 0; e < 64; e++)
            a += rn[e]*wp[e*64 + tid] + hn[e]*wx[e*64 + tid];
        hid[tid] = ftanh(a);
    }
    __syncthreads();
    {
        float a = l1b[tid];
#pragma unroll 8
        for (int f = 0; f < 64; f++) a += hid[f]*l1W[tid*64 + f];
        h2[tid] = ftanh(a);
    }
    __syncthreads();
    if (tid < 4) {
        float a = lb[tid];
#pragma unroll 8
        for (int j = 0; j < 128; j++) a += h2[j]*lW[tid*128 + j];
        outp[b*4 + tid] = a;
    }
}

// ---------------------------------------------------------------------------
extern "C" void kernel_launch(void* const* d_in, const int* in_sizes, int n_in,
                              void* d_out, int out_size)
{
    (void)in_sizes; (void)n_in; (void)out_size;

    const int*   s1   = (const int*)d_in[0];
    const int*   s2   = (const int*)d_in[1];
    const int*   s1l  = (const int*)d_in[2];
    const int*   s2l  = (const int*)d_in[3];
    const float* s1s  = (const float*)d_in[4];
    /* d_in[5] = s2_s, unused by the reference */
    const float* emb  = (const float*)d_in[6];
    const float* Wih1 = (const float*)d_in[7];
    const float* Whh1 = (const float*)d_in[8];
    const float* bih1 = (const float*)d_in[9];
    const float* bhh1 = (const float*)d_in[10];
    const float* Wih2 = (const float*)d_in[11];
    const float* Whh2 = (const float*)d_in[12];
    const float* bih2 = (const float*)d_in[13];
    const float* bhh2 = (const float*)d_in[14];
    const float* wy   = (const float*)d_in[15];
    const float* wh   = (const float*)d_in[16];
    const float* wv   = (const float*)d_in[17];
    const float* wp   = (const float*)d_in[18];
    const float* wx   = (const float*)d_in[19];
    const float* wr   = (const float*)d_in[20];
    const float* wt   = (const float*)d_in[21];
    const float* l1W  = (const float*)d_in[22];
    const float* l1b  = (const float*)d_in[23];
    const float* lW   = (const float*)d_in[24];
    const float* lb   = (const float*)d_in[25];
    float* outp = (float*)d_out;

    cudaFuncSetAttribute(attn_kernel,
                         cudaFuncAttributeMaxDynamicSharedMemorySize, ATT_SMEM);

    float* xp1; cudaGetSymbolAddress((void**)&xp1, g_xp1);
    float* xp2; cudaGetSymbolAddress((void**)&xp2, g_xp2);

    xproj_kernel<<<dim3((Bq*Sq)/32, 2), 256>>>(
        s1, s2, emb, Wih1, bih1, bhh1, Wih2, bih2, bhh2, xp1, xp2);
    lstm_fused_kernel<<<Bq, 256>>>(xp1, Whh1, xp2, Whh2, s1l);
    base_kernel<<<dim3(24, Bq), 256>>>(wy, wh);
    attn_kernel<<<Bq*2, 384, ATT_SMEM>>>(wv, wr, wt, s1s);
    final_kernel<<<Bq, 128>>>(s2l, wp, wx, l1W, l1b, lW, lb, outp);
}

// round 17
// speedup vs baseline: 1.0120x; 1.0058x over previous
#include <cuda_runtime.h>
#include <cstdint>
#include <math.h>

#define Bq 64
#define Sq 384
#define Eq 64
#define Dq 50
#define Gq 256   // 4*E
#define SL 192   // attention rows per cluster CTA (Sq/2)

// scratch (allocation-free rule: __device__ globals)
__device__ float g_h1[Bq*Sq*Eq];
__device__ float g_c1[Bq*Sq*Eq];
__device__ float g_out[Bq*Sq*Eq];
__device__ float g_base[Bq*Sq*Eq];
__device__ float g_Rt[Bq*Sq*Eq];
__device__ float g_xp1[Bq*Sq*Gq];
__device__ float g_xp2[Bq*Sq*Gq];

// ---- fast transcendentals (err ~1e-6, well under the 1e-3 gate) ----------
__device__ __forceinline__ float rcp_fast(float x){
    float r; asm("rcp.approx.f32 %0, %1;" : "=f"(r) : "f"(x)); return r;
}
__device__ __forceinline__ float ftanh(float x){
    float t = __expf(-2.f * fabsf(x));
    float y = (1.f - t) * rcp_fast(1.f + t);
    return copysignf(y, x);
}
__device__ __forceinline__ float fsig(float x){
    return rcp_fast(1.f + __expf(-x));
}
__device__ __forceinline__ uint32_t smem_u32(const void* p){
    uint32_t a;
    asm("{ .reg .u64 t; cvta.to.shared.u64 t, %1; cvt.u32.u64 %0, t; }"
        : "=r"(a) : "l"(p));
    return a;
}
__device__ __forceinline__ uint32_t mapa_u32(uint32_t addr, uint32_t rank){
    uint32_t r;
    asm("mapa.shared::cluster.u32 %0, %1, %2;" : "=r"(r) : "r"(addr), "r"(rank));
    return r;
}
__device__ __forceinline__ void st_cluster_f32(uint32_t addr, float v){
    asm volatile("st.shared::cluster.f32 [%0], %1;" :: "r"(addr), "f"(v) : "memory");
}
__device__ __forceinline__ void mbar_init(uint32_t addr, uint32_t count){
    asm volatile("mbarrier.init.shared.b64 [%0], %1;" :: "r"(addr), "r"(count) : "memory");
}
__device__ __forceinline__ void mbar_arrive_remote(uint32_t addr){
    asm volatile("mbarrier.arrive.release.cluster.shared::cluster.b64 _, [%0];"
                 :: "r"(addr) : "memory");
}
__device__ __forceinline__ void mbar_wait_parity(uint32_t addr, uint32_t parity){
    uint32_t done;
    asm volatile(
        "{\n\t.reg .pred p;\n\t"
        "mbarrier.try_wait.parity.acquire.cluster.shared::cta.b64 p, [%1], %2;\n\t"
        "selp.b32 %0, 1, 0, p;\n\t}"
        : "=r"(done) : "r"(addr), "r"(parity) : "memory");
    while (!done) {
        asm volatile(
            "{\n\t.reg .pred p;\n\t"
            "mbarrier.try_wait.parity.acquire.cluster.shared::cta.b64 p, [%1], %2, 0x989680;\n\t"
            "selp.b32 %0, 1, 0, p;\n\t}"
            : "=r"(done) : "r"(addr), "r"(parity) : "memory");
    }
}
__device__ __forceinline__ void cluster_sync(){
    asm volatile("barrier.cluster.arrive.aligned;" ::: "memory");
    asm volatile("barrier.cluster.wait.aligned;"   ::: "memory");
}

// ---------------------------------------------------------------------------
// Input projection (both sentences in one launch; blockIdx.y selects set):
// xp[b,s,g] = emb[tok[b,s]] @ Wih[g,:] + bih[g] + bhh[g]
// ---------------------------------------------------------------------------
__global__ __launch_bounds__(256) void xproj_kernel(
    const int* __restrict__ t1, const int* __restrict__ t2,
    const float* __restrict__ emb,
    const float* __restrict__ Wih1, const float* __restrict__ bih1,
    const float* __restrict__ bhh1,
    const float* __restrict__ Wih2, const float* __restrict__ bih2,
    const float* __restrict__ bhh2,
    float* __restrict__ xp1, float* __restrict__ xp2)
{
    __shared__ float xs[32][Dq];
    __shared__ int   tk[32];
    int set = blockIdx.y;
    const int*   toks = set ? t2 : t1;
    const float* Wih  = set ? Wih2 : Wih1;
    const float* bih  = set ? bih2 : bih1;
    const float* bhh  = set ? bhh2 : bhh1;
    float*       xp   = set ? xp2 : xp1;

    int row0 = blockIdx.x * 32;
    int j = threadIdx.x;

    if (j < 32) tk[j] = toks[row0 + j];
    __syncthreads();
    for (int i = j; i < 32*Dq; i += 256) {
        int r = i / Dq, k = i % Dq;
        xs[r][k] = emb[tk[r]*Dq + k];
    }

    float w[Dq];
#pragma unroll
    for (int k = 0; k < Dq; k++) w[k] = Wih[j*Dq + k];
    float bias = bih[j] + bhh[j];
    __syncthreads();

#pragma unroll 4
    for (int r = 0; r < 32; r++) {
        float acc = bias;
#pragma unroll
        for (int k = 0; k < Dq; k++) acc += w[k]*xs[r][k];
        xp[(row0 + r)*Gq + j] = acc;
    }
}

// ---------------------------------------------------------------------------
// FUSED recurrent LSTM: one CTA per batch b runs LSTM1 then LSTM2 (phase 2's
// gather reads only this CTA's own phase-1 output — same-thread RAW through
// gmem, no inter-CTA dependency). Per phase: R6 best-measured shape.
// ---------------------------------------------------------------------------
__global__ __launch_bounds__(256) void lstm_fused_kernel(
    const float* __restrict__ xp1, const float* __restrict__ Whh1,
    const float* __restrict__ xp2, const float* __restrict__ Whh2,
    const int* __restrict__ iidx)
{
    __shared__ __align__(16) float hs[Eq];
    __shared__ float gs[Gq];

    int b = blockIdx.x, j = threadIdx.x;
    float whh[Eq];

    // ---- phase 1: LSTM1, zero init, writes g_h1 and g_c1 ----
#pragma unroll
    for (int k = 0; k < Eq; k++) whh[k] = Whh1[j*Eq + k];
    float c = 0.f;
    if (j < Eq) hs[j] = 0.f;
    __syncthreads();

    {
        const float* xpb = xp1 + (size_t)b*Sq*Gq + j;
        float xv = xpb[0];
        for (int t = 0; t < Sq; t++) {
            const float4* h4 = (const float4*)hs;
            float a0 = xv, a1 = 0.f, a2 = 0.f, a3 = 0.f;
#pragma unroll
            for (int k = 0; k < 4; k++) {
                float4 v0 = h4[4*k], v1 = h4[4*k+1], v2 = h4[4*k+2], v3 = h4[4*k+3];
                a0 += whh[16*k   ]*v0.x + whh[16*k+1 ]*v0.y + whh[16*k+2 ]*v0.z + whh[16*k+3 ]*v0.w;
                a1 += whh[16*k+4 ]*v1.x + whh[16*k+5 ]*v1.y + whh[16*k+6 ]*v1.z + whh[16*k+7 ]*v1.w;
                a2 += whh[16*k+8 ]*v2.x + whh[16*k+9 ]*v2.y + whh[16*k+10]*v2.z + whh[16*k+11]*v2.w;
                a3 += whh[16*k+12]*v3.x + whh[16*k+13]*v3.y + whh[16*k+14]*v3.z + whh[16*k+15]*v3.w;
            }
            float acc = (a0 + a1) + (a2 + a3);
            if (t + 1 < Sq) xv = xpb[(t+1)*Gq];
            gs[j] = acc;
            __syncthreads();

            if (j < Eq) {
                float ig = fsig(gs[j]);
                float fg = fsig(gs[Eq + j]);
                float gg = ftanh(gs[2*Eq + j]);
                float og = fsig(gs[3*Eq + j]);
                c = fg*c + ig*gg;
                float h = og*ftanh(c);
                hs[j] = h;
                g_h1[(b*Sq + t)*Eq + j] = h;
                g_c1[(b*Sq + t)*Eq + j] = c;
            }
            __syncthreads();
        }
    }

    // ---- phase 2: LSTM2, gathered init (own CTA's data), writes g_out ----
#pragma unroll
    for (int k = 0; k < Eq; k++) whh[k] = Whh2[j*Eq + k];
    c = 0.f;
    if (j < Eq) {
        int idx = iidx[b*Eq + j];          // s1_len is (B,1,E)
        hs[j] = g_h1[(b*Sq + idx)*Eq + j]; // written by THIS thread in phase 1
        c     = g_c1[(b*Sq + idx)*Eq + j];
    }
    __syncthreads();

    {
        const float* xpb = xp2 + (size_t)b*Sq*Gq + j;
        float xv = xpb[0];
        for (int t = 0; t < Sq; t++) {
            const float4* h4 = (const float4*)hs;
            float a0 = xv, a1 = 0.f, a2 = 0.f, a3 = 0.f;
#pragma unroll
            for (int k = 0; k < 4; k++) {
                float4 v0 = h4[4*k], v1 = h4[4*k+1], v2 = h4[4*k+2], v3 = h4[4*k+3];
                a0 += whh[16*k   ]*v0.x + whh[16*k+1 ]*v0.y + whh[16*k+2 ]*v0.z + whh[16*k+3 ]*v0.w;
                a1 += whh[16*k+4 ]*v1.x + whh[16*k+5 ]*v1.y + whh[16*k+6 ]*v1.z + whh[16*k+7 ]*v1.w;
                a2 += whh[16*k+8 ]*v2.x + whh[16*k+9 ]*v2.y + whh[16*k+10]*v2.z + whh[16*k+11]*v2.w;
                a3 += whh[16*k+12]*v3.x + whh[16*k+13]*v3.y + whh[16*k+14]*v3.z + whh[16*k+15]*v3.w;
            }
            float acc = (a0 + a1) + (a2 + a3);
            if (t + 1 < Sq) xv = xpb[(t+1)*Gq];
            gs[j] = acc;
            __syncthreads();

            if (j < Eq) {
                float ig = fsig(gs[j]);
                float fg = fsig(gs[Eq + j]);
                float gg = ftanh(gs[2*Eq + j]);
                float og = fsig(gs[3*Eq + j]);
                c = fg*c + ig*gg;
                float h = og*ftanh(c);
                hs[j] = h;
                g_out[(b*Sq + t)*Eq + j] = h;
            }
            __syncthreads();
        }
    }
}

// ---------------------------------------------------------------------------
// base[b,s,:] = h1[b,s,:] @ wy + out[b,s,:] @ wh
// ---------------------------------------------------------------------------
__global__ __launch_bounds__(256) void base_kernel(
    const float* __restrict__ wy, const float* __restrict__ wh)
{
    __shared__ float wys[Eq*Eq], whs[Eq*Eq];
    __shared__ float ht[16][Eq], ot[16][Eq];

    int b  = blockIdx.y;
    int s0 = blockIdx.x * 16;
    int tid = threadIdx.x;

    for (int i = tid; i < Eq*Eq; i += 256) { wys[i] = wy[i]; whs[i] = wh[i]; }
    for (int i = tid; i < 16*Eq; i += 256) {
        int s = i >> 6, k = i & 63;
        ht[s][k] = g_h1 [(b*Sq + s0 + s)*Eq + k];
        ot[s][k] = g_out[(b*Sq + s0 + s)*Eq + k];
    }
    __syncthreads();

    int sl = tid >> 4;
    int e0 = (tid & 15) * 4;
    float acc[4] = {0.f, 0.f, 0.f, 0.f};
#pragma unroll 8
    for (int k = 0; k < Eq; k++) {
        float hv = ht[sl][k], ov = ot[sl][k];
#pragma unroll
        for (int u = 0; u < 4; u++)
            acc[u] += hv*wys[k*Eq + e0 + u] + ov*whs[k*Eq + e0 + u];
    }
    float* dst = &g_base[(b*Sq + s0 + sl)*Eq + e0];
#pragma unroll
    for (int u = 0; u < 4; u++) dst[u] = acc[u];
}

// ---------------------------------------------------------------------------
// Attention scan, 2-CTA cluster per batch row.
// REGISTER-PRESSURE FIX: tb eliminated via exact identity
//   tb*tr = (w*tb)*(tr/w)  ->  b = fma(wtb, trw, 1),  trw = tr/w from p1.
// Per-thread arrays: wtb[32] + hreg[32] (+ wcol[32] for p1) = 96 (was 128).
// w==0 guarded by winv=0 (element contributes exactly 0, matching w*tanh=0).
// p2 quad-rcp batching (1 MUFU / 4 elems); p3 from registers.
// ---------------------------------------------------------------------------
#define ATT_FLOATS (4 + 2*68 + 4 + 4*64 + 12*64 + 16)
#define ATT_SMEM   (ATT_FLOATS*4)

__global__ __launch_bounds__(384) __cluster_dims__(2, 1, 1)
void attn_kernel(
    const float* __restrict__ wvec, const float* __restrict__ wr,
    const float* __restrict__ wt,   const float* __restrict__ s1s)
{
    extern __shared__ float sm[];
    // sm[0..3]: mbarrier (8B) + pad
    float* imp    = sm + 4;              // 2*68 import slots (peer writes here)
    float* r_s    = imp + 2*68 + 4;      // 64 (16B aligned: 4+136+4 = 144)
    float* trw_s  = r_s + 64;            // 64  tanh(r@wr)/w  (guarded)
    float* wtr_s  = trw_s + 64;          // 64  w*tanh(r@wr)
    float* trwt_s = wtr_s + 64;          // 64  tanh(r@wt)
    float* part   = trwt_s + 64;         // 12*64
    float* red    = part + 12*64;        // 16

    int cta  = blockIdx.x;
    int b    = cta >> 1;
    uint32_t rank = cta & 1u;
    int tid  = threadIdx.x;
    int lane = tid & 31, wid = tid >> 5;

    uint32_t mbar_local  = smem_u32(sm);
    uint32_t mbar_remote = mapa_u32(mbar_local, rank ^ 1u);
    uint32_t imp_remote  = mapa_u32(smem_u32(imp), rank ^ 1u);

    if (tid == 0) mbar_init(mbar_local, 64);

    int half = lane & 1;
    int row  = wid*16 + (lane >> 1);     // p2 row for this thread (0..191)

    // p1 weights: thread tid<256 -> output o=tid>>1, rows hh*32..+32
    float wcol[32];
    float wv_o = 0.f, winv_o = 0.f;
    if (tid < 256) {
        int o = tid >> 1, hh = tid & 1;
        const float* wsrc = (o < 64) ? (wr + o) : (wt + o - 64);
#pragma unroll
        for (int k = 0; k < 32; k++) wcol[k] = wsrc[(hh*32 + k)*Eq];
        if (o < 64 && hh == 0) {
            wv_o = wvec[o];
            winv_o = (wv_o != 0.f) ? (1.f / wv_o) : 0.f;
        }
    }

    const int gofs = b*Sq*Eq + (int)rank*SL*Eq;

    // loop-invariant per-thread registers: w-scaled wtb only (p2 slice)
    float wtb[32];
    {
        const float* bsrc = &g_base[gofs + row*Eq + half*32];
        const float* wsrc = wvec + half*32;
#pragma unroll
        for (int k = 0; k < 32; k++)
            wtb[k] = wsrc[k]*ftanh(bsrc[k]);
    }
    // loop-invariant h registers for p3: rows wid*16..+15, cols 2*lane..+1
    float hreg[32];
    {
        const float* hsrc = &g_h1[gofs + (wid*16)*Eq + lane*2];
#pragma unroll
        for (int si = 0; si < 16; si++) {
            float2 hv = *(const float2*)&hsrc[si*Eq];
            hreg[2*si]   = hv.x;
            hreg[2*si+1] = hv.y;
        }
    }
    float m1 = s1s[b*Sq + (int)rank*SL + row];
    if (tid < 64) r_s[tid] = 0.f;
    __syncthreads();
    cluster_sync();   // peer's mbarrier init visible before any remote arrive

    for (int t = 0; t < Sq; t++) {
        // p1: tr = tanh(r@wr) -> exports trw = tr/w and wtr = w*tr;
        //     trwt = tanh(r@wt); 2 threads per output
        if (tid < 256) {
            int o = tid >> 1, hh = tid & 1;
            const float4* r4 = (const float4*)(r_s + hh*32);
            float a0 = 0.f, a1 = 0.f;
#pragma unroll
            for (int q = 0; q < 8; q += 2) {
                float4 v0 = r4[q], v1 = r4[q+1];
                a0 += wcol[4*q  ]*v0.x + wcol[4*q+1]*v0.y
                    + wcol[4*q+2]*v0.z + wcol[4*q+3]*v0.w;
                a1 += wcol[4*q+4]*v1.x + wcol[4*q+5]*v1.y
                    + wcol[4*q+6]*v1.z + wcol[4*q+7]*v1.w;
            }
            float s_ = a0 + a1;
            s_ += __shfl_xor_sync(0xffffffffu, s_, 1);
            if (hh == 0) {
                float v = ftanh(s_);
                if (o < 64) { trw_s[o] = v*winv_o; wtr_s[o] = wv_o*v; }
                else trwt_s[o-64] = v;
            }
        }
        __syncthreads();

        // p2: score for `row` (2 threads/row, 32 elems each), quad-rcp form,
        // b_i = 1 + wtb_i*trw_i  (== 1 + tb_i*tr_i exactly up to rounding)
        float sc = 0.f;
        {
            const float4* tr4 = (const float4*)(trw_s + half*32);
            const float4* wr4 = (const float4*)(wtr_s + half*32);
#pragma unroll
            for (int q = 0; q < 8; q++) {
                float4 tv = tr4[q], wv = wr4[q];
                float b0 = fmaf(wtb[4*q  ], tv.x, 1.f);
                float b1 = fmaf(wtb[4*q+1], tv.y, 1.f);
                float b2 = fmaf(wtb[4*q+2], tv.z, 1.f);
                float b3 = fmaf(wtb[4*q+3], tv.w, 1.f);
                float wa0 = wtb[4*q  ] + wv.x;
                float wa1 = wtb[4*q+1] + wv.y;
                float wa2 = wtb[4*q+2] + wv.z;
                float wa3 = wtb[4*q+3] + wv.w;
                float n01 = fmaf(wa1, b0, wa0*b1);
                float n23 = fmaf(wa3, b2, wa2*b3);
                float d01 = b0*b1, d23 = b2*b3;
                float num = fmaf(n23, d01, n01*d23);
                sc = fmaf(num, rcp_fast(d01*d23), sc);
            }
        }
        sc += __shfl_xor_sync(0xffffffffu, sc, 1);
        sc = m1*sc - (1.f - m1)*1e12f;
        float p = __expf(sc);

        // warp sum of p (each p duplicated in a lane pair -> halve)
        float v = p;
#pragma unroll
        for (int o = 16; o > 0; o >>= 1) v += __shfl_xor_sync(0xffffffffu, v, o);
        if (lane == 0) red[wid] = 0.5f*v;

        // p3: h.p partials from REGISTERS (16 rows x 2 e-cols per thread)
        {
            float a0 = 0.f, a1 = 0.f;
#pragma unroll
            for (int si = 0; si < 16; si++) {
                float pv = __shfl_sync(0xffffffffu, p, 2*si);
                a0 = fmaf(hreg[2*si],   pv, a0);
                a1 = fmaf(hreg[2*si+1], pv, a1);
            }
            part[wid*64 + lane*2]     = a0;
            part[wid*64 + lane*2 + 1] = a1;
        }
        __syncthreads();

        // p5: combine partials, exchange with peer, update r
        if (tid < 64) {
            float nl = 0.f;
#pragma unroll
            for (int g = 0; g < 12; g++) nl += part[g*64 + tid];
            float sl_ = 0.f;
#pragma unroll
            for (int i = 0; i < 12; i++) sl_ += red[i];

            int slot = (t & 1) * 68;
            st_cluster_f32(imp_remote + (slot + tid)*4, nl);
            if (tid == 0) st_cluster_f32(imp_remote + (slot + 64)*4, sl_);
            mbar_arrive_remote(mbar_remote);           // release (64 arrivals)
            mbar_wait_parity(mbar_local, (uint32_t)(t & 1));

            float pn = imp[slot + tid];
            float ps = imp[slot + 64];
            float rn = (nl + pn)*rcp_fast(sl_ + ps) + trwt_s[tid];
            r_s[tid] = rn;
            if (rank == 0) g_Rt[(b*Sq + t)*Eq + tid] = rn;
        }
        __syncthreads();
    }
    cluster_sync();   // no CTA exits while peer may still write our smem
}

// ---------------------------------------------------------------------------
// Final gathers + MLP head
// ---------------------------------------------------------------------------
__global__ __launch_bounds__(128) void final_kernel(
    const int* __restrict__ s2len,
    const float* __restrict__ wp, const float* __restrict__ wx,
    const float* __restrict__ l1W, const float* __restrict__ l1b,
    const float* __restrict__ lW,  const float* __restrict__ lb,
    float* __restrict__ outp)
{
    __shared__ float rn[64], hn[64], hid[64], h2[128];
    int b = blockIdx.x, tid = threadIdx.x;

    if (tid < 64) {
        int idx = s2len[b*64 + tid];
        rn[tid] = g_Rt [(b*Sq + idx)*Eq + tid];
        hn[tid] = g_out[(b*Sq + idx)*Eq + tid];
    }
    __syncthreads();
    if (tid < 64) {
        float a = 0.f;
#pragma unroll 8
        for (int e = 0; e < 64; e++)
            a += rn[e]*wp[e*64 + tid] + hn[e]*wx[e*64 + tid];
        hid[tid] = ftanh(a);
    }
    __syncthreads();
    {
        float a = l1b[tid];
#pragma unroll 8
        for (int f = 0; f < 64; f++) a += hid[f]*l1W[tid*64 + f];
        h2[tid] = ftanh(a);
    }
    __syncthreads();
    if (tid < 4) {
        float a = lb[tid];
#pragma unroll 8
        for (int j = 0; j < 128; j++) a += h2[j]*lW[tid*128 + j];
        outp[b*4 + tid] = a;
    }
}

// ---------------------------------------------------------------------------
extern "C" void kernel_launch(void* const* d_in, const int* in_sizes, int n_in,
                              void* d_out, int out_size)
{
    (void)in_sizes; (void)n_in; (void)out_size;

    const int*   s1   = (const int*)d_in[0];
    const int*   s2   = (const int*)d_in[1];
    const int*   s1l  = (const int*)d_in[2];
    const int*   s2l  = (const int*)d_in[3];
    const float* s1s  = (const float*)d_in[4];
    /* d_in[5] = s2_s, unused by the reference */
    const float* emb  = (const float*)d_in[6];
    const float* Wih1 = (const float*)d_in[7];
    const float* Whh1 = (const float*)d_in[8];
    const float* bih1 = (const float*)d_in[9];
    const float* bhh1 = (const float*)d_in[10];
    const float* Wih2 = (const float*)d_in[11];
    const float* Whh2 = (const float*)d_in[12];
    const float* bih2 = (const float*)d_in[13];
    const float* bhh2 = (const float*)d_in[14];
    const float* wy   = (const float*)d_in[15];
    const float* wh   = (const float*)d_in[16];
    const float* wv   = (const float*)d_in[17];
    const float* wp   = (const float*)d_in[18];
    const float* wx   = (const float*)d_in[19];
    const float* wr   = (const float*)d_in[20];
    const float* wt   = (const float*)d_in[21];
    const float* l1W  = (const float*)d_in[22];
    const float* l1b  = (const float*)d_in[23];
    const float* lW   = (const float*)d_in[24];
    const float* lb   = (const float*)d_in[25];
    float* outp = (float*)d_out;

    cudaFuncSetAttribute(attn_kernel,
                         cudaFuncAttributeMaxDynamicSharedMemorySize, ATT_SMEM);

    float* xp1; cudaGetSymbolAddress((void**)&xp1, g_xp1);
    float* xp2; cudaGetSymbolAddress((void**)&xp2, g_xp2);

    xproj_kernel<<<dim3((Bq*Sq)/32, 2), 256>>>(
        s1, s2, emb, Wih1, bih1, bhh1, Wih2, bih2, bhh2, xp1, xp2);
    lstm_fused_kernel<<<Bq, 256>>>(xp1, Whh1, xp2, Whh2, s1l);
    base_kernel<<<dim3(24, Bq), 256>>>(wy, wh);
    attn_kernel<<<Bq*2, 384, ATT_SMEM>>>(wv, wr, wt, s1s);
    final_kernel<<<Bq, 128>>>(s2l, wp, wx, l1W, l1b, lW, lb, outp);
}